// round 1
// baseline (speedup 1.0000x reference)
#include <cuda_runtime.h>
#include <cstdint>

// Problem constants (fixed by setup_inputs)
#define DIM   128
#define LMAX  60000
#define CMAX  30000
#define NITER 8

// ---------------- scratch (device globals; no allocations allowed) ----------
__device__ float g_tmp    [(size_t)LMAX * DIM];      // MLP hidden (shared L/C)
__device__ float g_l2c_msg[(size_t)LMAX * DIM];
__device__ float g_c2l_msg[(size_t)CMAX * DIM];
__device__ float g_l2l_msg[(size_t)LMAX * DIM];
__device__ float g_aggr_c [(size_t)CMAX * DIM];
__device__ float g_aggr_l [(size_t)LMAX * DIM];
__device__ float g_gi_c   [(size_t)CMAX * 3 * DIM];
__device__ float g_gh_c   [(size_t)CMAX * 3 * DIM];
__device__ float g_gi_l   [(size_t)LMAX * 3 * DIM];
__device__ float g_gh_l   [(size_t)LMAX * 3 * DIM];

// ---------------- generic fp32 GEMM: out[N, NOtot] = act(A @ W^T + bias) ----
// A is one or two [N,128] sources (concat along K). W is [NOtot, Ktot] row-major.
// Block computes a 64-row x 128-col tile. 256 threads, each 8x4 outputs.
#define BM 64
#define BN 128
#define BK 32

__global__ __launch_bounds__(256) void gemm128(
    const float* __restrict__ A0, const float* __restrict__ A1,
    const float* __restrict__ W,  const float* __restrict__ bias,
    float* __restrict__ out,
    int N, int NOtot, int Ktot, int relu, int perm)
{
    __shared__ __align__(16) float sA[BM][BK];
    __shared__ __align__(16) float sW[BK][BN + 4];

    const int m0 = blockIdx.x * BM;
    const int n0 = blockIdx.y * BN;
    const int t  = threadIdx.x;
    const int tx = t & 31;   // column group: cols n0 + 4*tx .. +3
    const int ty = t >> 5;   // row group: rows m0 + 8*ty .. +7

    float acc[8][4];
#pragma unroll
    for (int r = 0; r < 8; r++)
#pragma unroll
        for (int c = 0; c < 4; c++) acc[r][c] = 0.f;

    for (int kc = 0; kc < Ktot; kc += 128) {
        const float* __restrict__ A = (kc == 0) ? A0 : A1;
        for (int kb = 0; kb < 128; kb += BK) {
            __syncthreads();
            // load A tile (coalesced 128B per warp), zero-pad rows >= N
#pragma unroll
            for (int i = 0; i < (BM * BK) / 256; i++) {
                int idx = t + i * 256;
                int r = idx >> 5, k = idx & 31;
                int row = m0 + r;
                float v = 0.f;
                if (row < N) {
                    int arow = perm ? (row ^ 1) : row;
                    v = A[(size_t)arow * 128 + kb + k];
                }
                sA[r][k] = v;
            }
            // load W tile transposed: sW[k][j] = W[(n0+j)*Ktot + kc+kb+k]
#pragma unroll
            for (int i = 0; i < (BK * BN) / 256; i++) {
                int idx = t + i * 256;
                int j = idx >> 5, k = idx & 31;
                sW[k][j] = W[(size_t)(n0 + j) * Ktot + kc + kb + k];
            }
            __syncthreads();
#pragma unroll
            for (int k = 0; k < BK; k++) {
                float4 w = *(const float4*)&sW[k][tx * 4];
#pragma unroll
                for (int r = 0; r < 8; r++) {
                    float a = sA[ty * 8 + r][k];
                    acc[r][0] += a * w.x;
                    acc[r][1] += a * w.y;
                    acc[r][2] += a * w.z;
                    acc[r][3] += a * w.w;
                }
            }
        }
    }

    float4 b4 = *(const float4*)&bias[n0 + tx * 4];
#pragma unroll
    for (int r = 0; r < 8; r++) {
        int row = m0 + ty * 8 + r;
        if (row < N) {
            float4 v;
            v.x = acc[r][0] + b4.x;
            v.y = acc[r][1] + b4.y;
            v.z = acc[r][2] + b4.z;
            v.w = acc[r][3] + b4.w;
            if (relu) {
                v.x = fmaxf(v.x, 0.f); v.y = fmaxf(v.y, 0.f);
                v.z = fmaxf(v.z, 0.f); v.w = fmaxf(v.w, 0.f);
            }
            *(float4*)&out[(size_t)row * NOtot + n0 + tx * 4] = v;
        }
    }
}

// ---------------- zero fill -------------------------------------------------
__global__ void zerof(float* __restrict__ p, int n)
{
    int i = blockIdx.x * blockDim.x + threadIdx.x;
    if (i < n) p[i] = 0.f;
}

// ---------------- edge scatter-add: aggr[dst[e],:] += msg[src[e],:] ---------
__global__ void scatter_add(const float* __restrict__ msg,
                            const int* __restrict__ src,
                            const int* __restrict__ dst,
                            float* __restrict__ aggr, int E)
{
    int t = blockIdx.x * blockDim.x + threadIdx.x;
    int e = t >> 5;
    if (e >= E) return;
    int c = (t & 31) * 4;
    int s = src[e], d = dst[e];
    float4 v = *(const float4*)(msg + (size_t)s * DIM + c);
    float* p = aggr + (size_t)d * DIM + c;
    atomicAdd(p + 0, v.x);
    atomicAdd(p + 1, v.y);
    atomicAdd(p + 2, v.z);
    atomicAdd(p + 3, v.w);
}

// ---------------- GRU elementwise gate math ---------------------------------
__device__ __forceinline__ float sigmoidf_(float x) { return 1.f / (1.f + expf(-x)); }

__global__ void gru_elem(const float* __restrict__ gi, const float* __restrict__ gh,
                         const float* __restrict__ h, float* __restrict__ hnew, int N)
{
    int idx = blockIdx.x * blockDim.x + threadIdx.x;
    if (idx >= N * DIM) return;
    int row = idx >> 7, col = idx & 127;
    const float* gir = gi + (size_t)row * 3 * DIM;
    const float* ghr = gh + (size_t)row * 3 * DIM;
    float ir = gir[col], iz = gir[DIM + col], in_ = gir[2 * DIM + col];
    float hr = ghr[col], hz = ghr[DIM + col], hn  = ghr[2 * DIM + col];
    float r = sigmoidf_(ir + hr);
    float z = sigmoidf_(iz + hz);
    float n = tanhf(in_ + r * hn);
    hnew[idx] = (1.f - z) * n + z * h[idx];
}

// ---------------- launch ----------------------------------------------------
extern "C" void kernel_launch(void* const* d_in, const int* in_sizes, int n_in,
                              void* d_out, int out_size)
{
    const int D = DIM;
    const int E = in_sizes[2];
    const int L = in_sizes[4] / D;
    const int C = in_sizes[5] / D;

    const int*   l_edge = (const int*)d_in[2];
    const int*   c_edge = (const int*)d_in[3];
    const float* l_emb0 = (const float*)d_in[4];
    const float* c_emb0 = (const float*)d_in[5];

    const float* l2c_W0 = (const float*)d_in[6];
    const float* l2c_b0 = (const float*)d_in[7];
    const float* l2c_W1 = (const float*)d_in[8];
    const float* l2c_b1 = (const float*)d_in[9];
    const float* c2l_W0 = (const float*)d_in[10];
    const float* c2l_b0 = (const float*)d_in[11];
    const float* c2l_W1 = (const float*)d_in[12];
    const float* c2l_b1 = (const float*)d_in[13];
    const float* l2l_W0 = (const float*)d_in[14];
    const float* l2l_b0 = (const float*)d_in[15];
    const float* l2l_W1 = (const float*)d_in[16];
    const float* l2l_b1 = (const float*)d_in[17];
    const float* c_Wih  = (const float*)d_in[18];
    const float* c_Whh  = (const float*)d_in[19];
    const float* c_bih  = (const float*)d_in[20];
    const float* c_bhh  = (const float*)d_in[21];
    const float* l_Wih  = (const float*)d_in[22];
    const float* l_Whh  = (const float*)d_in[23];
    const float* l_bih  = (const float*)d_in[24];
    const float* l_bhh  = (const float*)d_in[25];

    float* out   = (float*)d_out;
    float* louts = out;                            // [9, L, D]
    float* couts = out + (size_t)(NITER + 1) * L * D;  // [9, C, D]

    float *tmp, *l2c_msg, *c2l_msg, *l2l_msg, *aggr_c, *aggr_l, *gi_c, *gh_c, *gi_l, *gh_l;
    cudaGetSymbolAddress((void**)&tmp,     g_tmp);
    cudaGetSymbolAddress((void**)&l2c_msg, g_l2c_msg);
    cudaGetSymbolAddress((void**)&c2l_msg, g_c2l_msg);
    cudaGetSymbolAddress((void**)&l2l_msg, g_l2l_msg);
    cudaGetSymbolAddress((void**)&aggr_c,  g_aggr_c);
    cudaGetSymbolAddress((void**)&aggr_l,  g_aggr_l);
    cudaGetSymbolAddress((void**)&gi_c,    g_gi_c);
    cudaGetSymbolAddress((void**)&gh_c,    g_gh_c);
    cudaGetSymbolAddress((void**)&gi_l,    g_gi_l);
    cudaGetSymbolAddress((void**)&gh_l,    g_gh_l);

    // iteration-0 slices = inputs
    cudaMemcpyAsync(louts, l_emb0, (size_t)L * D * sizeof(float), cudaMemcpyDeviceToDevice);
    cudaMemcpyAsync(couts, c_emb0, (size_t)C * D * sizeof(float), cudaMemcpyDeviceToDevice);

    const dim3 gL((L + BM - 1) / BM, 1);
    const dim3 gC((C + BM - 1) / BM, 1);
    const dim3 gL3((L + BM - 1) / BM, 3);
    const dim3 gC3((C + BM - 1) / BM, 3);
    const int eThreads = (E * 32 + 255) / 256;

    for (int it = 0; it < NITER; it++) {
        const float* l_prev = louts + (size_t)it * L * D;
        const float* c_prev = couts + (size_t)it * C * D;
        float* l_next = louts + (size_t)(it + 1) * L * D;
        float* c_next = couts + (size_t)(it + 1) * C * D;

        // l2c message MLP: [L,D]
        gemm128<<<gL, 256>>>(l_prev, nullptr, l2c_W0, l2c_b0, tmp,     L, 128, 128, 1, 0);
        gemm128<<<gL, 256>>>(tmp,    nullptr, l2c_W1, l2c_b1, l2c_msg, L, 128, 128, 0, 0);
        // c2l message MLP: [C,D]
        gemm128<<<gC, 256>>>(c_prev, nullptr, c2l_W0, c2l_b0, tmp,     C, 128, 128, 1, 0);
        gemm128<<<gC, 256>>>(tmp,    nullptr, c2l_W1, c2l_b1, c2l_msg, C, 128, 128, 0, 0);
        // l2l message MLP on pair-swapped rows (row j reads l_prev[j^1])
        gemm128<<<gL, 256>>>(l_prev, nullptr, l2l_W0, l2l_b0, tmp,     L, 128, 128, 1, 1);
        gemm128<<<gL, 256>>>(tmp,    nullptr, l2l_W1, l2l_b1, l2l_msg, L, 128, 128, 0, 0);

        // aggregate literal messages into clauses
        zerof<<<(C * D + 255) / 256, 256>>>(aggr_c, C * D);
        scatter_add<<<eThreads, 256>>>(l2c_msg, l_edge, c_edge, aggr_c, E);

        // clause GRU
        gemm128<<<gC3, 256>>>(aggr_c, nullptr, c_Wih, c_bih, gi_c, C, 384, 128, 0, 0);
        gemm128<<<gC3, 256>>>(c_prev, nullptr, c_Whh, c_bhh, gh_c, C, 384, 128, 0, 0);
        gru_elem<<<(C * D + 255) / 256, 256>>>(gi_c, gh_c, c_prev, c_next, C);

        // aggregate clause messages into literals
        zerof<<<(L * D + 255) / 256, 256>>>(aggr_l, L * D);
        scatter_add<<<eThreads, 256>>>(c2l_msg, c_edge, l_edge, aggr_l, E);

        // literal GRU (input = concat(c2l_aggr, l2l_msg) -> K=256)
        gemm128<<<gL3, 256>>>(aggr_l, l2l_msg, l_Wih, l_bih, gi_l, L, 384, 256, 0, 0);
        gemm128<<<gL3, 256>>>(l_prev, nullptr, l_Whh, l_bhh, gh_l, L, 384, 128, 0, 0);
        gru_elem<<<(L * D + 255) / 256, 256>>>(gi_l, gh_l, l_prev, l_next, L);
    }
}

// round 3
// speedup vs baseline: 1.9055x; 1.9055x over previous
#include <cuda_runtime.h>
#include <cstdint>

// Problem constants (fixed by setup_inputs)
#define DIM   128
#define LMAX  60000
#define CMAX  30000
#define EMAX  360000
#define NITER 8

// ---------------- scratch (device globals; no allocations allowed) ----------
__device__ float g_tmp    [(size_t)LMAX * DIM];
__device__ float g_l2c_msg[(size_t)LMAX * DIM];
__device__ float g_c2l_msg[(size_t)CMAX * DIM];
__device__ float g_l2l_msg[(size_t)LMAX * DIM];
__device__ float g_aggr_c [(size_t)CMAX * DIM];
__device__ float g_aggr_l [(size_t)LMAX * DIM];
__device__ float g_gi_c   [(size_t)CMAX * 3 * DIM];
__device__ float g_gh_c   [(size_t)CMAX * 3 * DIM];
__device__ float g_gi_l   [(size_t)LMAX * 3 * DIM];
__device__ float g_gh_l   [(size_t)LMAX * 3 * DIM];
// CSR scratch
__device__ int g_cnt_c[CMAX];
__device__ int g_cnt_l[LMAX];
__device__ int g_off_c[CMAX + 1];
__device__ int g_off_l[LMAX + 1];
__device__ int g_cur_c[CMAX];
__device__ int g_cur_l[LMAX];
__device__ int g_src_c[EMAX];   // for each clause slot: source literal
__device__ int g_src_l[EMAX];   // for each literal slot: source clause

// ======================= helpers =============================================
__device__ __forceinline__ uint32_t smem_u32(const void* p) {
    uint32_t a;
    asm("{ .reg .u64 t; cvta.to.shared.u64 t, %1; cvt.u32.u64 %0, t; }"
        : "=r"(a) : "l"(p));
    return a;
}

__device__ __forceinline__ void split_tf32(float x, uint32_t& hi, uint32_t& lo) {
    uint32_t h;
    asm("cvt.rna.tf32.f32 %0, %1;" : "=r"(h) : "f"(x));
    float r = x - __uint_as_float(h);
    uint32_t l;
    asm("cvt.rna.tf32.f32 %0, %1;" : "=r"(l) : "f"(r));
    hi = h; lo = l;
}

__device__ __forceinline__ void cp16(uint32_t dst, const void* src, int sz) {
    asm volatile("cp.async.cg.shared.global [%0], [%1], 16, %2;"
                 :: "r"(dst), "l"(src), "r"(sz) : "memory");
}

__device__ __forceinline__ void mma_tf32(float* d, const uint32_t* a,
                                         uint32_t b0, uint32_t b1) {
    asm volatile(
        "mma.sync.aligned.m16n8k8.row.col.f32.tf32.tf32.f32 "
        "{%0,%1,%2,%3}, {%4,%5,%6,%7}, {%8,%9}, {%0,%1,%2,%3};"
        : "+f"(d[0]), "+f"(d[1]), "+f"(d[2]), "+f"(d[3])
        : "r"(a[0]), "r"(a[1]), "r"(a[2]), "r"(a[3]), "r"(b0), "r"(b1));
}

// ======================= 3xTF32 mma.sync GEMM ================================
// out[N, NOtot] (128-col tile at n0) = act(A @ W^T + bias)
// A: one or two [N,128] fp32 sources concatenated along K; W: [NOtot,Ktot] row-major.
// CTA tile 128x128; 8 warps in 4x2 -> warp tile 32(M) x 64(N); K chunks of 16.
#define GBK    16
#define SSTR   20                 // padded smem row stride (floats): conflict-free
#define ATILEF (128 * SSTR)       // 2560 floats
#define STAGEF (2 * ATILEF)       // A + W per stage

__global__ __launch_bounds__(256, 2)
void gemm_mma(const float* __restrict__ A0, const float* __restrict__ A1,
              const float* __restrict__ W,  const float* __restrict__ bias,
              float* __restrict__ out,
              int N, int NOtot, int Ktot, int relu, int perm)
{
    __shared__ __align__(16) float smem[2 * STAGEF];   // 40 KB

    const int t    = threadIdx.x;
    const int wid  = t >> 5;
    const int lane = t & 31;
    const int m0   = blockIdx.x * 128;
    const int n0   = blockIdx.y * 128;

    const int wm = (wid & 3) * 32;     // warp M offset in tile
    const int wn = (wid >> 2) * 64;    // warp N offset in tile

    const uint32_t sbase = smem_u32(smem);

    float acc[2][8][4];
#pragma unroll
    for (int mt = 0; mt < 2; mt++)
#pragma unroll
        for (int nt = 0; nt < 8; nt++)
#pragma unroll
            for (int i = 0; i < 4; i++) acc[mt][nt][i] = 0.f;

    const int nch = Ktot >> 4;

    // ---- loader lambda-ish: issue cp.asyncs for chunk ch into buffer buf ----
    auto load_chunk = [&](int ch, int buf) {
        const int kc = ch << 4;
        const float* __restrict__ Asrc = (kc < 128) ? A0 : A1;
        const int acol = kc & 127;
        const uint32_t abase = sbase + (uint32_t)buf * STAGEF * 4;
        const uint32_t wbase = abase + ATILEF * 4;
#pragma unroll
        for (int i = 0; i < 2; i++) {
            int idx = t + i * 256;          // 0..511
            int r = idx >> 2, j = idx & 3;
            // A
            int grow = m0 + r;
            int arow = (grow < N) ? (perm ? (grow ^ 1) : grow) : 0;
            const float* gp = Asrc + (size_t)arow * 128 + acol + j * 4;
            cp16(abase + (uint32_t)(r * SSTR + j * 4) * 4, gp, (grow < N) ? 16 : 0);
            // W
            const float* wp = W + (size_t)(n0 + r) * Ktot + kc + j * 4;
            cp16(wbase + (uint32_t)(r * SSTR + j * 4) * 4, wp, 16);
        }
    };

    load_chunk(0, 0);
    asm volatile("cp.async.commit_group;" ::: "memory");

    for (int ch = 0; ch < nch; ch++) {
        if (ch + 1 < nch) load_chunk(ch + 1, (ch + 1) & 1);
        asm volatile("cp.async.commit_group;" ::: "memory");
        asm volatile("cp.async.wait_group 1;" ::: "memory");
        __syncthreads();

        const float* sA = smem + (ch & 1) * STAGEF;
        const float* sW = sA + ATILEF;

#pragma unroll
        for (int ks = 0; ks < 2; ks++) {
            const int kb = ks * 8 + (lane & 3);
            uint32_t ah[2][4], al[2][4];
#pragma unroll
            for (int mt = 0; mt < 2; mt++) {
                int r = wm + mt * 16 + (lane >> 2);
                float x0 = sA[r * SSTR + kb];
                float x1 = sA[(r + 8) * SSTR + kb];
                float x2 = sA[r * SSTR + kb + 4];
                float x3 = sA[(r + 8) * SSTR + kb + 4];
                split_tf32(x0, ah[mt][0], al[mt][0]);
                split_tf32(x1, ah[mt][1], al[mt][1]);
                split_tf32(x2, ah[mt][2], al[mt][2]);
                split_tf32(x3, ah[mt][3], al[mt][3]);
            }
#pragma unroll
            for (int nt = 0; nt < 8; nt++) {
                int c = wn + nt * 8 + (lane >> 2);
                float y0 = sW[c * SSTR + kb];
                float y1 = sW[c * SSTR + kb + 4];
                uint32_t bh0, bl0, bh1, bl1;
                split_tf32(y0, bh0, bl0);
                split_tf32(y1, bh1, bl1);
#pragma unroll
                for (int mt = 0; mt < 2; mt++) {
                    mma_tf32(acc[mt][nt], ah[mt], bh0, bh1);
                    mma_tf32(acc[mt][nt], ah[mt], bl0, bl1);
                    mma_tf32(acc[mt][nt], al[mt], bh0, bh1);
                }
            }
        }
        __syncthreads();
    }

    // ---- epilogue: bias + optional relu, write fp32 ----
#pragma unroll
    for (int mt = 0; mt < 2; mt++) {
#pragma unroll
        for (int nt = 0; nt < 8; nt++) {
            int row = m0 + wm + mt * 16 + (lane >> 2);
            int col = n0 + wn + nt * 8 + 2 * (lane & 3);
            float2 b2 = *(const float2*)(bias + col);
            float* d = acc[mt][nt];
            if (row < N) {
                float2 o = {d[0] + b2.x, d[1] + b2.y};
                if (relu) { o.x = fmaxf(o.x, 0.f); o.y = fmaxf(o.y, 0.f); }
                *(float2*)(out + (size_t)row * NOtot + col) = o;
            }
            if (row + 8 < N) {
                float2 o = {d[2] + b2.x, d[3] + b2.y};
                if (relu) { o.x = fmaxf(o.x, 0.f); o.y = fmaxf(o.y, 0.f); }
                *(float2*)(out + (size_t)(row + 8) * NOtot + col) = o;
            }
        }
    }
}

// ======================= CSR build ===========================================
__global__ void hist2(const int* __restrict__ l_e, const int* __restrict__ c_e,
                      int* __restrict__ cnt_l, int* __restrict__ cnt_c, int E)
{
    int i = blockIdx.x * blockDim.x + threadIdx.x;
    if (i < E) {
        atomicAdd(&cnt_l[l_e[i]], 1);
        atomicAdd(&cnt_c[c_e[i]], 1);
    }
}

// exclusive scan of cnt[0..n) -> off[0..n]; single block of 1024
__global__ void exscan(const int* __restrict__ cnt, int* __restrict__ off, int n)
{
    __shared__ int part[1024];
    const int t = threadIdx.x;
    const int chunk = (n + 1023) >> 10;
    const int b = t * chunk;
    const int e = min(b + chunk, n);
    int s = 0;
    for (int i = b; i < e; i++) s += cnt[i];
    part[t] = s;
    __syncthreads();
    for (int d = 1; d < 1024; d <<= 1) {
        int v = (t >= d) ? part[t - d] : 0;
        __syncthreads();
        if (t >= d) part[t] += v;
        __syncthreads();
    }
    int run = (t == 0) ? 0 : part[t - 1];
    for (int i = b; i < e; i++) { off[i] = run; run += cnt[i]; }
    if (t == 0) off[n] = part[1023];
}

__global__ void fill2(const int* __restrict__ l_e, const int* __restrict__ c_e,
                      int* __restrict__ cur_l, int* __restrict__ cur_c,
                      int* __restrict__ src_l, int* __restrict__ src_c, int E)
{
    int i = blockIdx.x * blockDim.x + threadIdx.x;
    if (i < E) {
        int l = l_e[i], c = c_e[i];
        src_c[atomicAdd(&cur_c[c], 1)] = l;   // clause c gathers msg from literal l
        src_l[atomicAdd(&cur_l[l], 1)] = c;   // literal l gathers msg from clause c
    }
}

// ======================= gather-sum (replaces atomic scatter) ================
// one warp per node; lane handles 4 contiguous columns (float4)
__global__ __launch_bounds__(256)
void gather(const float* __restrict__ msg, const int* __restrict__ off,
            const int* __restrict__ srcs, float* __restrict__ aggr, int n)
{
    int node = blockIdx.x * 8 + (threadIdx.x >> 5);
    if (node >= n) return;
    int lane = threadIdx.x & 31;
    int b = off[node], e = off[node + 1];
    float4 acc = {0.f, 0.f, 0.f, 0.f};
    for (int i = b; i < e; i++) {
        const float4 v = *((const float4*)(msg + (size_t)srcs[i] * DIM) + lane);
        acc.x += v.x; acc.y += v.y; acc.z += v.z; acc.w += v.w;
    }
    *((float4*)(aggr + (size_t)node * DIM) + lane) = acc;
}

// ---------------- GRU elementwise gate math ----------------------------------
__device__ __forceinline__ float sigmoidf_(float x) { return 1.f / (1.f + expf(-x)); }

__global__ void gru_elem(const float* __restrict__ gi, const float* __restrict__ gh,
                         const float* __restrict__ h, float* __restrict__ hnew, int N)
{
    int idx = blockIdx.x * blockDim.x + threadIdx.x;
    if (idx >= N * DIM) return;
    int row = idx >> 7, col = idx & 127;
    const float* gir = gi + (size_t)row * 3 * DIM;
    const float* ghr = gh + (size_t)row * 3 * DIM;
    float ir = gir[col], iz = gir[DIM + col], in_ = gir[2 * DIM + col];
    float hr = ghr[col], hz = ghr[DIM + col], hn  = ghr[2 * DIM + col];
    float r = sigmoidf_(ir + hr);
    float z = sigmoidf_(iz + hz);
    float n = tanhf(in_ + r * hn);
    hnew[idx] = (1.f - z) * n + z * h[idx];
}

// ---------------- launch ------------------------------------------------------
extern "C" void kernel_launch(void* const* d_in, const int* in_sizes, int n_in,
                              void* d_out, int out_size)
{
    const int D = DIM;
    const int E = in_sizes[2];
    const int L = in_sizes[4] / D;
    const int C = in_sizes[5] / D;

    const int*   l_edge = (const int*)d_in[2];
    const int*   c_edge = (const int*)d_in[3];
    const float* l_emb0 = (const float*)d_in[4];
    const float* c_emb0 = (const float*)d_in[5];

    const float* l2c_W0 = (const float*)d_in[6];
    const float* l2c_b0 = (const float*)d_in[7];
    const float* l2c_W1 = (const float*)d_in[8];
    const float* l2c_b1 = (const float*)d_in[9];
    const float* c2l_W0 = (const float*)d_in[10];
    const float* c2l_b0 = (const float*)d_in[11];
    const float* c2l_W1 = (const float*)d_in[12];
    const float* c2l_b1 = (const float*)d_in[13];
    const float* l2l_W0 = (const float*)d_in[14];
    const float* l2l_b0 = (const float*)d_in[15];
    const float* l2l_W1 = (const float*)d_in[16];
    const float* l2l_b1 = (const float*)d_in[17];
    const float* c_Wih  = (const float*)d_in[18];
    const float* c_Whh  = (const float*)d_in[19];
    const float* c_bih  = (const float*)d_in[20];
    const float* c_bhh  = (const float*)d_in[21];
    const float* l_Wih  = (const float*)d_in[22];
    const float* l_Whh  = (const float*)d_in[23];
    const float* l_bih  = (const float*)d_in[24];
    const float* l_bhh  = (const float*)d_in[25];

    float* out   = (float*)d_out;
    float* louts = out;                                // [9, L, D]
    float* couts = out + (size_t)(NITER + 1) * L * D;  // [9, C, D]

    float *tmp, *l2c_msg, *c2l_msg, *l2l_msg, *aggr_c, *aggr_l, *gi_c, *gh_c, *gi_l, *gh_l;
    cudaGetSymbolAddress((void**)&tmp,     g_tmp);
    cudaGetSymbolAddress((void**)&l2c_msg, g_l2c_msg);
    cudaGetSymbolAddress((void**)&c2l_msg, g_c2l_msg);
    cudaGetSymbolAddress((void**)&l2l_msg, g_l2l_msg);
    cudaGetSymbolAddress((void**)&aggr_c,  g_aggr_c);
    cudaGetSymbolAddress((void**)&aggr_l,  g_aggr_l);
    cudaGetSymbolAddress((void**)&gi_c,    g_gi_c);
    cudaGetSymbolAddress((void**)&gh_c,    g_gh_c);
    cudaGetSymbolAddress((void**)&gi_l,    g_gi_l);
    cudaGetSymbolAddress((void**)&gh_l,    g_gh_l);

    int *cnt_c, *cnt_l, *off_c, *off_l, *cur_c, *cur_l, *src_c, *src_l;
    cudaGetSymbolAddress((void**)&cnt_c, g_cnt_c);
    cudaGetSymbolAddress((void**)&cnt_l, g_cnt_l);
    cudaGetSymbolAddress((void**)&off_c, g_off_c);
    cudaGetSymbolAddress((void**)&off_l, g_off_l);
    cudaGetSymbolAddress((void**)&cur_c, g_cur_c);
    cudaGetSymbolAddress((void**)&cur_l, g_cur_l);
    cudaGetSymbolAddress((void**)&src_c, g_src_c);
    cudaGetSymbolAddress((void**)&src_l, g_src_l);

    // ---- CSR build (edge structure is static across iterations) ----
    cudaMemsetAsync(cnt_c, 0, (size_t)C * sizeof(int));
    cudaMemsetAsync(cnt_l, 0, (size_t)L * sizeof(int));
    hist2<<<(E + 255) / 256, 256>>>(l_edge, c_edge, cnt_l, cnt_c, E);
    exscan<<<1, 1024>>>(cnt_c, off_c, C);
    exscan<<<1, 1024>>>(cnt_l, off_l, L);
    cudaMemcpyAsync(cur_c, off_c, (size_t)C * sizeof(int), cudaMemcpyDeviceToDevice);
    cudaMemcpyAsync(cur_l, off_l, (size_t)L * sizeof(int), cudaMemcpyDeviceToDevice);
    fill2<<<(E + 255) / 256, 256>>>(l_edge, c_edge, cur_l, cur_c, src_l, src_c, E);

    // iteration-0 slices = inputs
    cudaMemcpyAsync(louts, l_emb0, (size_t)L * D * sizeof(float), cudaMemcpyDeviceToDevice);
    cudaMemcpyAsync(couts, c_emb0, (size_t)C * D * sizeof(float), cudaMemcpyDeviceToDevice);

    const int gLx = (L + 127) / 128;
    const int gCx = (C + 127) / 128;
    const dim3 gL(gLx, 1), gC(gCx, 1), gL3(gLx, 3), gC3(gCx, 3);

    for (int it = 0; it < NITER; it++) {
        const float* l_prev = louts + (size_t)it * L * D;
        const float* c_prev = couts + (size_t)it * C * D;
        float* l_next = louts + (size_t)(it + 1) * L * D;
        float* c_next = couts + (size_t)(it + 1) * C * D;

        // l2c message MLP
        gemm_mma<<<gL, 256>>>(l_prev, nullptr, l2c_W0, l2c_b0, tmp,     L, 128, 128, 1, 0);
        gemm_mma<<<gL, 256>>>(tmp,    nullptr, l2c_W1, l2c_b1, l2c_msg, L, 128, 128, 0, 0);
        // c2l message MLP
        gemm_mma<<<gC, 256>>>(c_prev, nullptr, c2l_W0, c2l_b0, tmp,     C, 128, 128, 1, 0);
        gemm_mma<<<gC, 256>>>(tmp,    nullptr, c2l_W1, c2l_b1, c2l_msg, C, 128, 128, 0, 0);
        // l2l message MLP on pair-swapped rows
        gemm_mma<<<gL, 256>>>(l_prev, nullptr, l2l_W0, l2l_b0, tmp,     L, 128, 128, 1, 1);
        gemm_mma<<<gL, 256>>>(tmp,    nullptr, l2l_W1, l2l_b1, l2l_msg, L, 128, 128, 0, 0);

        // aggregate literal messages into clauses (gather, no atomics)
        gather<<<(C + 7) / 8, 256>>>(l2c_msg, off_c, src_c, aggr_c, C);

        // clause GRU
        gemm_mma<<<gC3, 256>>>(aggr_c, nullptr, c_Wih, c_bih, gi_c, C, 384, 128, 0, 0);
        gemm_mma<<<gC3, 256>>>(c_prev, nullptr, c_Whh, c_bhh, gh_c, C, 384, 128, 0, 0);
        gru_elem<<<(C * D + 255) / 256, 256>>>(gi_c, gh_c, c_prev, c_next, C);

        // aggregate clause messages into literals (gather)
        gather<<<(L + 7) / 8, 256>>>(c2l_msg, off_l, src_l, aggr_l, L);

        // literal GRU (input = concat(c2l_aggr, l2l_msg), K=256)
        gemm_mma<<<gL3, 256>>>(aggr_l, l2l_msg, l_Wih, l_bih, gi_l, L, 384, 256, 0, 0);
        gemm_mma<<<gL3, 256>>>(l_prev, nullptr, l_Whh, l_bhh, gh_l, L, 384, 128, 0, 0);
        gru_elem<<<(L * D + 255) / 256, 256>>>(gi_l, gh_l, l_prev, l_next, L);
    }
}